// round 1
// baseline (speedup 1.0000x reference)
#include <cuda_runtime.h>
#include <cstdint>

// Problem constants
#define M_ROWS   131072          // 64 * 2048
#define D_ATOM   256
#define D_HID    512
#define D_OUT    256
#define T_ANG    2048
#define N_ATOMS  256
#define GRID_Y   (M_ROWS / 128)  // 1024
#define BN_EPS   1e-5

// Scratch (device globals: allocation-free rule)
__device__ float g_h[(size_t)M_ROWS * D_HID];      // 268 MB intermediate h (pre-BN)
__device__ float g_psum[D_HID * GRID_Y];           // per-(col, m-tile) partial sums
__device__ float g_psumsq[D_HID * GRID_Y];
__device__ float g_s[D_HID];                       // folded BN scale
__device__ float g_t[D_HID];                       // folded BN shift

// ---------------- helpers ----------------

__device__ __forceinline__ unsigned long long dup2(float x) {
    unsigned long long r;
    unsigned u = __float_as_uint(x);
    asm("mov.b64 %0, {%1, %1};" : "=l"(r) : "r"(u));
    return r;
}

__device__ __forceinline__ void fma2(unsigned long long& acc,
                                     unsigned long long a,
                                     unsigned long long b) {
    asm("fma.rn.f32x2 %0, %1, %2, %0;" : "+l"(acc) : "l"(a), "l"(b));
}

__device__ __forceinline__ float2 unpk(unsigned long long v) {
    float2 f;
    f.x = __uint_as_float((unsigned)(v & 0xffffffffULL));
    f.y = __uint_as_float((unsigned)(v >> 32));
    return f;
}

// ---------------- kernel 1: gather + GEMM1 (+ column partial stats) ----------------
// grid (4, 1024), 256 threads. Tile: 128(M) x 128(N), K=256 fully staged in smem.
// dynamic smem: xs[256][128] (gathered x, [k][m] layout) + ws[2][8*128] (W1 slices)

__global__ void __launch_bounds__(256, 1)
gemm1_kernel(const float* __restrict__ z, const void* __restrict__ tbl_raw,
             const float* __restrict__ W1, const float* __restrict__ b1)
{
    extern __shared__ float smem[];
    float* xs = smem;                       // 256*128 floats = 128 KB
    float* ws = smem + 256 * 128;           // 2 * 1024 floats = 8 KB

    __shared__ int sb0[128], sb1[128], sb2[128];
    __shared__ int s_is64;

    const int tid = threadIdx.x;
    const int bx  = blockIdx.x;             // n tile 0..3
    const int by  = blockIdx.y;             // m tile 0..1023
    const int mbase = by * 128;
    const int nbase = bx * 128;

    // detect int64 vs int32 table (values are 0..255, so int64 high words are 0)
    if (tid == 0) {
        const unsigned* t32 = (const unsigned*)tbl_raw;
        unsigned accu = 0;
        #pragma unroll
        for (int i = 0; i < 16; i++) accu |= t32[2 * i + 1];
        s_is64 = (accu == 0) ? 1 : 0;
    }
    __syncthreads();

    if (tid < 128) {
        int r = mbase + tid;
        int b = r >> 11;                    // r / 2048
        int i0, i1, i2;
        if (s_is64) {
            const long long* tp = (const long long*)tbl_raw + (long long)r * 3;
            i0 = (int)tp[0]; i1 = (int)tp[1]; i2 = (int)tp[2];
        } else {
            const int* tp = (const int*)tbl_raw + (long long)r * 3;
            i0 = tp[0]; i1 = tp[1]; i2 = tp[2];
        }
        sb0[tid] = (b * N_ATOMS + i0) * D_ATOM;
        sb1[tid] = (b * N_ATOMS + i1) * D_ATOM;
        sb2[tid] = (b * N_ATOMS + i2) * D_ATOM;
    }
    __syncthreads();

    // gather x rows into xs[k][m] (transposed): warp lanes = m (coalesce-ish z reads,
    // conflict-free smem stores)
    {
        const int w = tid >> 5, lane = tid & 31;
        const int m = ((w & 3) << 5) + lane;
        const float4* z0 = (const float4*)(z + sb0[m]);
        const float4* z1 = (const float4*)(z + sb1[m]);
        const float4* z2 = (const float4*)(z + sb2[m]);
        const int k4base = (w >> 2) << 5;
        #pragma unroll 4
        for (int j = 0; j < 32; j++) {
            int k4 = k4base + j;
            float4 v0 = z0[k4], v1 = z1[k4], v2 = z2[k4];
            float vx = v0.x + v1.x + v2.x;
            float vy = v0.y + v1.y + v2.y;
            float vz = v0.z + v1.z + v2.z;
            float vw = v0.w + v1.w + v2.w;
            int k = k4 << 2;
            xs[(k + 0) * 128 + m] = vx;
            xs[(k + 1) * 128 + m] = vy;
            xs[(k + 2) * 128 + m] = vz;
            xs[(k + 3) * 128 + m] = vw;
        }
    }

    const int tx = tid & 15, ty = tid >> 4;

    // W1 slice loader: thread loads one float4 per 8x128 slice
    const float* wptr = W1 + (size_t)(tid >> 5) * D_HID + nbase + ((tid & 31) << 2);
    {
        float4 w0 = *(const float4*)wptr;
        ((float4*)ws)[tid] = w0;
    }
    __syncthreads();

    unsigned long long acc[8][4];
    #pragma unroll
    for (int i = 0; i < 8; i++)
        #pragma unroll
        for (int j = 0; j < 4; j++) acc[i][j] = 0ULL;

    #pragma unroll 1
    for (int s = 0; s < 32; s++) {
        float4 pre;
        if (s < 31) pre = *(const float4*)(wptr + (size_t)(s + 1) * 8 * D_HID);
        const float* wsc = ws + (s & 1) * 1024;
        #pragma unroll
        for (int kk = 0; kk < 8; kk++) {
            const int k = s * 8 + kk;
            float4 a0 = *(const float4*)(xs + k * 128 + ty * 8);
            float4 a1 = *(const float4*)(xs + k * 128 + ty * 8 + 4);
            ulonglong2 b01 = *(const ulonglong2*)(wsc + kk * 128 + tx * 8);
            ulonglong2 b23 = *(const ulonglong2*)(wsc + kk * 128 + tx * 8 + 4);
            unsigned long long bp[4] = { b01.x, b01.y, b23.x, b23.y };
            float av[8] = { a0.x, a0.y, a0.z, a0.w, a1.x, a1.y, a1.z, a1.w };
            #pragma unroll
            for (int i = 0; i < 8; i++) {
                unsigned long long ad = dup2(av[i]);
                #pragma unroll
                for (int j = 0; j < 4; j++) fma2(acc[i][j], ad, bp[j]);
            }
        }
        if (s < 31) {
            ((float4*)(ws + ((s + 1) & 1) * 1024))[tid] = pre;
            __syncthreads();
        }
    }

    // epilogue: +b1, write h, per-column partial sums / sumsq (deterministic)
    float bb[8];
    #pragma unroll
    for (int j = 0; j < 8; j++) bb[j] = b1[nbase + tx * 8 + j];

    float cres[8][8];
    #pragma unroll
    for (int i = 0; i < 8; i++)
        #pragma unroll
        for (int j = 0; j < 4; j++) {
            float2 f = unpk(acc[i][j]);
            cres[i][2 * j]     = f.x + bb[2 * j];
            cres[i][2 * j + 1] = f.y + bb[2 * j + 1];
        }

    #pragma unroll
    for (int i = 0; i < 8; i++) {
        float4* dst = (float4*)(g_h + (size_t)(mbase + ty * 8 + i) * D_HID + nbase + tx * 8);
        dst[0] = make_float4(cres[i][0], cres[i][1], cres[i][2], cres[i][3]);
        dst[1] = make_float4(cres[i][4], cres[i][5], cres[i][6], cres[i][7]);
    }

    float csum[8], csq[8];
    #pragma unroll
    for (int j = 0; j < 8; j++) { csum[j] = 0.f; csq[j] = 0.f; }
    #pragma unroll
    for (int i = 0; i < 8; i++)
        #pragma unroll
        for (int j = 0; j < 8; j++) {
            float v = cres[i][j];
            csum[j] += v;
            csq[j]  += v * v;
        }

    float* red = smem;  // reuse (>= 16*128 floats available)
    __syncthreads();
    #pragma unroll
    for (int j = 0; j < 8; j++) red[ty * 128 + tx * 8 + j] = csum[j];
    __syncthreads();
    if (tid < 128) {
        float ssum = 0.f;
        #pragma unroll
        for (int q = 0; q < 16; q++) ssum += red[q * 128 + tid];
        g_psum[(nbase + tid) * GRID_Y + by] = ssum;
    }
    __syncthreads();
    #pragma unroll
    for (int j = 0; j < 8; j++) red[ty * 128 + tx * 8 + j] = csq[j];
    __syncthreads();
    if (tid < 128) {
        float ssum = 0.f;
        #pragma unroll
        for (int q = 0; q < 16; q++) ssum += red[q * 128 + tid];
        g_psumsq[(nbase + tid) * GRID_Y + by] = ssum;
    }
}

// ---------------- kernel 2: finalize BN stats -> folded affine ----------------
// grid (512), 256 threads; one block per hidden column.

__global__ void __launch_bounds__(256)
stats_kernel(const float* __restrict__ gamma, const float* __restrict__ beta)
{
    const int c = blockIdx.x;
    const int tid = threadIdx.x;
    double a1 = 0.0, a2 = 0.0;
    for (int i = tid; i < GRID_Y; i += 256) {
        a1 += (double)g_psum[c * GRID_Y + i];
        a2 += (double)g_psumsq[c * GRID_Y + i];
    }
    __shared__ double r1[256], r2[256];
    r1[tid] = a1; r2[tid] = a2;
    __syncthreads();
    for (int w = 128; w > 0; w >>= 1) {
        if (tid < w) { r1[tid] += r1[tid + w]; r2[tid] += r2[tid + w]; }
        __syncthreads();
    }
    if (tid == 0) {
        double mean = r1[0] / (double)M_ROWS;
        double var  = r2[0] / (double)M_ROWS - mean * mean;
        float sv = (float)((double)gamma[c] / sqrt(var + (double)BN_EPS));
        g_s[c] = sv;
        g_t[c] = beta[c] - (float)mean * sv;
    }
}

// ---------------- kernel 3: BN-affine + ReLU + GEMM2 ----------------
// grid (2, 1024), 256 threads. Tile 128x128, K=512 streamed in BK=16 slices,
// double-buffered with register prefetch. A is loaded from g_h with relu(h*s+t).

__global__ void __launch_bounds__(256, 1)
gemm2_kernel(const float* __restrict__ W2, const float* __restrict__ b2,
             float* __restrict__ out)
{
    __shared__ float as[2][16 * 128];
    __shared__ float bs[2][16 * 128];
    __shared__ float ss[D_HID], tt[D_HID];

    const int tid = threadIdx.x;
    const int bx  = blockIdx.x;   // 0..1
    const int by  = blockIdx.y;   // 0..1023
    const int mbase = by * 128;
    const int nbase = bx * 128;
    const int tx = tid & 15, ty = tid >> 4;

    ss[tid]       = g_s[tid];
    ss[tid + 256] = g_s[tid + 256];
    tt[tid]       = g_t[tid];
    tt[tid + 256] = g_t[tid + 256];
    __syncthreads();

    float4 va[2], vb[2];

    auto loadA = [&](int s) {
        #pragma unroll
        for (int q = 0; q < 2; q++) {
            int lin = q * 256 + tid;
            int k4 = lin >> 7, m = lin & 127;
            va[q] = *(const float4*)(g_h + (size_t)(mbase + m) * D_HID + s * 16 + k4 * 4);
        }
    };
    auto storeA = [&](int s, int buf) {
        #pragma unroll
        for (int q = 0; q < 2; q++) {
            int lin = q * 256 + tid;
            int k4 = lin >> 7, m = lin & 127;
            int k = s * 16 + k4 * 4;
            as[buf][(k4 * 4 + 0) * 128 + m] = fmaxf(fmaf(va[q].x, ss[k + 0], tt[k + 0]), 0.f);
            as[buf][(k4 * 4 + 1) * 128 + m] = fmaxf(fmaf(va[q].y, ss[k + 1], tt[k + 1]), 0.f);
            as[buf][(k4 * 4 + 2) * 128 + m] = fmaxf(fmaf(va[q].z, ss[k + 2], tt[k + 2]), 0.f);
            as[buf][(k4 * 4 + 3) * 128 + m] = fmaxf(fmaf(va[q].w, ss[k + 3], tt[k + 3]), 0.f);
        }
    };
    auto loadB = [&](int s) {
        #pragma unroll
        for (int q = 0; q < 2; q++) {
            int lin = q * 256 + tid;
            int row = lin >> 5, n4 = lin & 31;
            vb[q] = *(const float4*)(W2 + (size_t)(s * 16 + row) * D_OUT + nbase + n4 * 4);
        }
    };
    auto storeB = [&](int buf) {
        #pragma unroll
        for (int q = 0; q < 2; q++) {
            int lin = q * 256 + tid;
            int row = lin >> 5, n4 = lin & 31;
            *(float4*)(&bs[buf][row * 128 + n4 * 4]) = vb[q];
        }
    };

    loadA(0); loadB(0);
    storeA(0, 0); storeB(0);
    __syncthreads();

    unsigned long long acc[8][4];
    #pragma unroll
    for (int i = 0; i < 8; i++)
        #pragma unroll
        for (int j = 0; j < 4; j++) acc[i][j] = 0ULL;

    #pragma unroll 1
    for (int s = 0; s < 32; s++) {
        if (s < 31) { loadA(s + 1); loadB(s + 1); }
        const float* ac = as[s & 1];
        const float* bc = bs[s & 1];
        #pragma unroll
        for (int kk = 0; kk < 16; kk++) {
            float4 a0 = *(const float4*)(ac + kk * 128 + ty * 8);
            float4 a1 = *(const float4*)(ac + kk * 128 + ty * 8 + 4);
            ulonglong2 b01 = *(const ulonglong2*)(bc + kk * 128 + tx * 8);
            ulonglong2 b23 = *(const ulonglong2*)(bc + kk * 128 + tx * 8 + 4);
            unsigned long long bp[4] = { b01.x, b01.y, b23.x, b23.y };
            float av[8] = { a0.x, a0.y, a0.z, a0.w, a1.x, a1.y, a1.z, a1.w };
            #pragma unroll
            for (int i = 0; i < 8; i++) {
                unsigned long long ad = dup2(av[i]);
                #pragma unroll
                for (int j = 0; j < 4; j++) fma2(acc[i][j], ad, bp[j]);
            }
        }
        if (s < 31) {
            storeA(s + 1, (s + 1) & 1);
            storeB((s + 1) & 1);
            __syncthreads();
        }
    }

    float bb[8];
    #pragma unroll
    for (int j = 0; j < 8; j++) bb[j] = b2[nbase + tx * 8 + j];

    #pragma unroll
    for (int i = 0; i < 8; i++) {
        float cres[8];
        #pragma unroll
        for (int j = 0; j < 4; j++) {
            float2 f = unpk(acc[i][j]);
            cres[2 * j]     = f.x + bb[2 * j];
            cres[2 * j + 1] = f.y + bb[2 * j + 1];
        }
        float4* dst = (float4*)(out + (size_t)(mbase + ty * 8 + i) * D_OUT + nbase + tx * 8);
        dst[0] = make_float4(cres[0], cres[1], cres[2], cres[3]);
        dst[1] = make_float4(cres[4], cres[5], cres[6], cres[7]);
    }
}

// ---------------- launch ----------------

extern "C" void kernel_launch(void* const* d_in, const int* in_sizes, int n_in,
                              void* d_out, int out_size)
{
    const float* z     = (const float*)d_in[0];
    const void*  tbl   = d_in[1];                // int64 or int32 (auto-detected)
    const float* W1    = (const float*)d_in[2];
    const float* b1    = (const float*)d_in[3];
    const float* gamma = (const float*)d_in[4];
    const float* beta  = (const float*)d_in[5];
    const float* W2    = (const float*)d_in[6];
    const float* b2    = (const float*)d_in[7];
    float* out = (float*)d_out;

    const size_t smem1 = (size_t)(256 * 128 + 2 * 8 * 128) * sizeof(float); // 139264 B
    cudaFuncSetAttribute(gemm1_kernel, cudaFuncAttributeMaxDynamicSharedMemorySize,
                         (int)smem1);

    gemm1_kernel<<<dim3(4, GRID_Y), 256, smem1>>>(z, tbl, W1, b1);
    stats_kernel<<<512, 256>>>(gamma, beta);
    gemm2_kernel<<<dim3(2, GRID_Y), 256>>>(W2, b2, out);
}

// round 3
// speedup vs baseline: 2.7448x; 2.7448x over previous
#include <cuda_runtime.h>
#include <cuda_fp16.h>
#include <cstdint>

#define M_ROWS   131072
#define D_ATOM   256
#define D_HID    512
#define D_OUT    256
#define N_ATOMS  256
#define GRID_Y   (M_ROWS / 128)   // 1024
#define BN_EPS   1e-5

// ---------------- device scratch (allocation-free rule) ----------------
// X in packed split layout: [row][kchunk 0..7][hi 32 fp16 | lo 32 fp16] (1KB/row)
__device__ unsigned short g_Xc[(size_t)M_ROWS * 512];
// W1^T packed: [n 0..511][kchunk 0..7][hi32|lo32]
__device__ unsigned short g_W1c[(size_t)D_HID * 512];
// W2^T packed: [n 0..255][kchunk 0..15][hi32|lo32]
__device__ unsigned short g_W2c[(size_t)D_OUT * 1024];
__device__ float g_h[(size_t)M_ROWS * D_HID];        // 268 MB
__device__ float g_psum[D_HID * GRID_Y];
__device__ float g_psumsq[D_HID * GRID_Y];
__device__ float g_s[D_HID];
__device__ float g_t[D_HID];

// ---------------- helpers ----------------
__device__ __forceinline__ uint32_t smem_u32(const void* p) {
    uint32_t a;
    asm("{ .reg .u64 t; cvta.to.shared.u64 t, %1; cvt.u32.u64 %0, t; }" : "=r"(a) : "l"(p));
    return a;
}
__device__ __forceinline__ void cpa16(uint32_t sdst, const void* gsrc) {
    asm volatile("cp.async.cg.shared.global [%0], [%1], 16;" :: "r"(sdst), "l"(gsrc));
}
#define CP_COMMIT() asm volatile("cp.async.commit_group;" ::: "memory")
#define CP_WAIT(n)  asm volatile("cp.async.wait_group %0;" :: "n"(n) : "memory")

__device__ __forceinline__ void ldsm4(uint32_t* r, uint32_t addr) {
    asm volatile("ldmatrix.sync.aligned.m8n8.x4.shared.b16 {%0,%1,%2,%3}, [%4];"
                 : "=r"(r[0]), "=r"(r[1]), "=r"(r[2]), "=r"(r[3]) : "r"(addr));
}
__device__ __forceinline__ void hmma(float* d, const uint32_t* a, uint32_t b0, uint32_t b1) {
    asm volatile("mma.sync.aligned.m16n8k16.row.col.f32.f16.f16.f32 "
                 "{%0,%1,%2,%3},{%4,%5,%6,%7},{%8,%9},{%0,%1,%2,%3};"
                 : "+f"(d[0]), "+f"(d[1]), "+f"(d[2]), "+f"(d[3])
                 : "r"(a[0]), "r"(a[1]), "r"(a[2]), "r"(a[3]), "r"(b0), "r"(b1));
}
__device__ __forceinline__ unsigned short f2h(float x) {
    __half h = __float2half_rn(x);
    return *reinterpret_cast<unsigned short*>(&h);
}
__device__ __forceinline__ float h2f(unsigned short u) {
    __half h = *reinterpret_cast<__half*>(&u);
    return __half2float(h);
}
__device__ __forceinline__ uint32_t pk(unsigned short a, unsigned short b) {
    return (uint32_t)a | ((uint32_t)b << 16);
}

// stage smem layout: A[2][16KB], B[2][16KB]
#define SA(buf) ((buf) * 16384)
#define SB(buf) (32768 + (buf) * 16384)
#define DYN_BYTES 65536

// mma over one 128B-row stage (k=32, hi chunks 0-3, lo chunks 4-7)
__device__ __forceinline__ void mma_stage(const char* smem, int buf, int wm, int wn,
                                          int lane, float acc[2][8][4]) {
    uint32_t sa = smem_u32(smem + SA(buf));
    uint32_t sbm = smem_u32(smem + SB(buf));
    const int xr = lane & 15;
    const int cq = lane >> 4;
    #pragma unroll
    for (int ks = 0; ks < 2; ks++) {
        uint32_t ah[2][4], al[2][4];
        #pragma unroll
        for (int mi = 0; mi < 2; mi++) {
            int row = wm * 32 + mi * 16 + xr;
            uint32_t base = sa + row * 128;
            ldsm4(ah[mi], base + (((ks * 2 + cq) ^ (row & 7)) * 16));
            ldsm4(al[mi], base + (((4 + ks * 2 + cq) ^ (row & 7)) * 16));
        }
        uint32_t bh[4][4], bl[4][4];
        #pragma unroll
        for (int nq = 0; nq < 4; nq++) {
            int row = wn * 64 + nq * 16 + xr;
            uint32_t base = sbm + row * 128;
            ldsm4(bh[nq], base + (((ks * 2 + cq) ^ (row & 7)) * 16));
            ldsm4(bl[nq], base + (((4 + ks * 2 + cq) ^ (row & 7)) * 16));
        }
        #pragma unroll
        for (int mi = 0; mi < 2; mi++)
            #pragma unroll
            for (int nf = 0; nf < 8; nf++) {
                int nq = nf >> 1, p = nf & 1;
                hmma(acc[mi][nf], ah[mi], bh[nq][p], bh[nq][p + 2]);   // hh
                hmma(acc[mi][nf], ah[mi], bl[nq][p], bl[nq][p + 2]);   // hl
                hmma(acc[mi][nf], al[mi], bh[nq][p], bh[nq][p + 2]);   // lh
            }
    }
}

// ---------------- kernel: pack + split + transpose weights ----------------
__global__ void __launch_bounds__(256) prepw_kernel(const float* __restrict__ W1,
                                                    const float* __restrict__ W2) {
    int b = blockIdx.x, tid = threadIdx.x;
    if (b < D_HID) {
        int n = b, k = tid;                       // 0..255
        float v = W1[(size_t)k * D_HID + n];
        unsigned short hi = f2h(v);
        unsigned short lo = f2h(v - h2f(hi));
        size_t base = ((size_t)n * 8 + (k >> 5)) * 64;   // ushort index of 128B chunk
        g_W1c[base + (k & 31)]      = hi;
        g_W1c[base + 32 + (k & 31)] = lo;
    } else {
        int n = b - D_HID;
        #pragma unroll
        for (int q = 0; q < 2; q++) {
            int k = tid + q * 256;                // 0..511
            float v = W2[(size_t)k * D_OUT + n];
            unsigned short hi = f2h(v);
            unsigned short lo = f2h(v - h2f(hi));
            size_t base = ((size_t)n * 16 + (k >> 5)) * 64;
            g_W2c[base + (k & 31)]      = hi;
            g_W2c[base + 32 + (k & 31)] = lo;
        }
    }
}

// ---------------- kernel: gather 3-atom sum -> packed split X ----------------
__global__ void __launch_bounds__(256) gather_kernel(const float* __restrict__ z,
                                                     const void* __restrict__ tbl) {
    __shared__ int s_is64;
    int tid = threadIdx.x;
    if (tid == 0) {
        const unsigned* t32 = (const unsigned*)tbl;
        unsigned acc = 0;
        #pragma unroll
        for (int i = 0; i < 16; i++) acc |= t32[2 * i + 1];
        s_is64 = (acc == 0) ? 1 : 0;
    }
    __syncthreads();
    int w = tid >> 5, lane = tid & 31;
    long long r = (long long)blockIdx.x * 8 + w;
    int bidx = (int)(r >> 11);
    int i0, i1, i2;
    if (s_is64) {
        const long long* tp = (const long long*)tbl + r * 3;
        i0 = (int)tp[0]; i1 = (int)tp[1]; i2 = (int)tp[2];
    } else {
        const int* tp = (const int*)tbl + r * 3;
        i0 = tp[0]; i1 = tp[1]; i2 = tp[2];
    }
    const float4* z0 = (const float4*)(z + ((size_t)bidx * N_ATOMS + i0) * D_ATOM);
    const float4* z1 = (const float4*)(z + ((size_t)bidx * N_ATOMS + i1) * D_ATOM);
    const float4* z2 = (const float4*)(z + ((size_t)bidx * N_ATOMS + i2) * D_ATOM);
    int k4 = lane * 2;                            // covers k = lane*8 .. +7
    float vs[8];
    #pragma unroll
    for (int q = 0; q < 2; q++) {
        float4 a = z0[k4 + q], b = z1[k4 + q], c = z2[k4 + q];
        vs[q * 4 + 0] = a.x + b.x + c.x;
        vs[q * 4 + 1] = a.y + b.y + c.y;
        vs[q * 4 + 2] = a.z + b.z + c.z;
        vs[q * 4 + 3] = a.w + b.w + c.w;
    }
    unsigned short hb[8], lb[8];
    #pragma unroll
    for (int e = 0; e < 8; e++) {
        hb[e] = f2h(vs[e]);
        lb[e] = f2h(vs[e] - h2f(hb[e]));
    }
    uint4 vh = make_uint4(pk(hb[0], hb[1]), pk(hb[2], hb[3]), pk(hb[4], hb[5]), pk(hb[6], hb[7]));
    uint4 vl = make_uint4(pk(lb[0], lb[1]), pk(lb[2], lb[3]), pk(lb[4], lb[5]), pk(lb[6], lb[7]));
    uint4* g = (uint4*)g_Xc;
    size_t base = ((size_t)r * 8 + (lane >> 2)) * 8;   // uint4 index of 128B chunk
    g[base + (lane & 3)]     = vh;
    g[base + 4 + (lane & 3)] = vl;
}

// ---------------- kernel: GEMM1  h = X@W1 + b1  (+ per-tile column stats) ----------------
// grid (4, 1024), 256 threads (8 warps: 4m x 2n), tile 128x128, K=256 (8 stages of 32)
__global__ void __launch_bounds__(256) gemm1_kernel(const float* __restrict__ b1) {
    extern __shared__ char smem[];
    __shared__ float sbias[128];
    __shared__ float sps[2][128], sqs[2][128];

    const int tid = threadIdx.x, lane = tid & 31, wid = tid >> 5;
    const int wm = wid & 3, wn = wid >> 2;
    const int mbase = blockIdx.y * 128;
    const int nbase = blockIdx.x * 128;

    if (tid < 128) sbias[tid] = b1[nbase + tid];

    // prologue: stage 0
    {
        const char* gA = (const char*)g_Xc;
        const char* gB = (const char*)g_W1c;
        #pragma unroll
        for (int q = 0; q < 4; q++) {
            int u = q * 256 + tid, row = u >> 3, c = u & 7;
            cpa16(smem_u32(smem + SA(0)) + row * 128 + ((c ^ (row & 7)) * 16),
                  gA + ((size_t)(mbase + row) * 8 + 0) * 128 + c * 16);
            cpa16(smem_u32(smem + SB(0)) + row * 128 + ((c ^ (row & 7)) * 16),
                  gB + ((size_t)(nbase + row) * 8 + 0) * 128 + c * 16);
        }
        CP_COMMIT();
    }

    float acc[2][8][4];
    #pragma unroll
    for (int mi = 0; mi < 2; mi++)
        #pragma unroll
        for (int nf = 0; nf < 8; nf++)
            #pragma unroll
            for (int e = 0; e < 4; e++) acc[mi][nf][e] = 0.f;

    #pragma unroll 1
    for (int s = 0; s < 8; s++) {
        if (s + 1 < 8) {
            int nb = (s + 1) & 1;
            const char* gA = (const char*)g_Xc;
            const char* gB = (const char*)g_W1c;
            #pragma unroll
            for (int q = 0; q < 4; q++) {
                int u = q * 256 + tid, row = u >> 3, c = u & 7;
                cpa16(smem_u32(smem + SA(nb)) + row * 128 + ((c ^ (row & 7)) * 16),
                      gA + ((size_t)(mbase + row) * 8 + (s + 1)) * 128 + c * 16);
                cpa16(smem_u32(smem + SB(nb)) + row * 128 + ((c ^ (row & 7)) * 16),
                      gB + ((size_t)(nbase + row) * 8 + (s + 1)) * 128 + c * 16);
            }
            CP_COMMIT();
            CP_WAIT(1);
        } else {
            CP_WAIT(0);
        }
        __syncthreads();
        mma_stage(smem, s & 1, wm, wn, lane, acc);
        __syncthreads();
    }

    // ---- epilogue: +bias, stage fp32 tile in smem (swizzled), stats + coalesced h write
    const int t4 = lane >> 2, tc = lane & 3;
    #pragma unroll
    for (int mi = 0; mi < 2; mi++)
        #pragma unroll
        for (int nf = 0; nf < 8; nf++) {
            int c0 = wn * 64 + nf * 8 + tc * 2;
            float bb0 = sbias[c0], bb1 = sbias[c0 + 1];
            int colc = c0 >> 2, off = (c0 & 3) * 4;
            #pragma unroll
            for (int rr = 0; rr < 2; rr++) {
                int row = wm * 32 + mi * 16 + t4 + rr * 8;
                float v0 = acc[mi][nf][rr * 2] + bb0;
                float v1 = acc[mi][nf][rr * 2 + 1] + bb1;
                *(float2*)(smem + row * 512 + ((colc ^ (row & 7)) * 16) + off) =
                    make_float2(v0, v1);
            }
        }
    __syncthreads();

    // stats: 2 threads per column, 64 rows each (conflict-free swizzled column walk)
    {
        int col = tid & 127, half = tid >> 7;
        int colc = col >> 2, off = (col & 3) * 4;
        float s1 = 0.f, s2 = 0.f;
        #pragma unroll 4
        for (int r0 = 0; r0 < 64; r0++) {
            int row = half * 64 + r0;
            float v = *(const float*)(smem + row * 512 + ((colc ^ (row & 7)) * 16) + off);
            s1 += v;
            s2 = fmaf(v, v, s2);
        }
        sps[half][col] = s1;
        sqs[half][col] = s2;
    }
    __syncthreads();
    if (tid < 128) {
        g_psum  [(size_t)(nbase + tid) * GRID_Y + blockIdx.y] = sps[0][tid] + sps[1][tid];
        g_psumsq[(size_t)(nbase + tid) * GRID_Y + blockIdx.y] = sqs[0][tid] + sqs[1][tid];
    }

    // h write: 4096 uint4 units, coalesced
    {
        char* gh = (char*)g_h;
        #pragma unroll
        for (int q = 0; q < 16; q++) {
            int u = q * 256 + tid, row = u >> 5, c16 = u & 31;
            uint4 v = *(const uint4*)(smem + row * 512 + ((c16 ^ (row & 7)) * 16));
            *(uint4*)(gh + (size_t)(mbase + row) * 2048 + nbase * 4 + c16 * 16) = v;
        }
    }
}

// ---------------- kernel: BN stats finalize ----------------
__global__ void __launch_bounds__(256) stats_kernel(const float* __restrict__ gamma,
                                                    const float* __restrict__ beta) {
    const int c = blockIdx.x, tid = threadIdx.x;
    double a1 = 0.0, a2 = 0.0;
    for (int i = tid; i < GRID_Y; i += 256) {
        a1 += (double)g_psum[c * GRID_Y + i];
        a2 += (double)g_psumsq[c * GRID_Y + i];
    }
    __shared__ double r1[256], r2[256];
    r1[tid] = a1; r2[tid] = a2;
    __syncthreads();
    for (int w = 128; w > 0; w >>= 1) {
        if (tid < w) { r1[tid] += r1[tid + w]; r2[tid] += r2[tid + w]; }
        __syncthreads();
    }
    if (tid == 0) {
        double mean = r1[0] / (double)M_ROWS;
        double var  = r2[0] / (double)M_ROWS - mean * mean;
        float sv = (float)((double)gamma[c] / sqrt(var + (double)BN_EPS));
        g_s[c] = sv;
        g_t[c] = beta[c] - (float)mean * sv;
    }
}

// ---------------- kernel: GEMM2  out = relu(affine(h))@W2 + b2 ----------------
// grid (2, 1024), 256 threads, tile 128x128, K=512 (16 stages of 32)
__global__ void __launch_bounds__(256) gemm2_kernel(const float* __restrict__ b2,
                                                    float* __restrict__ out) {
    extern __shared__ char smem[];
    __shared__ float ss[D_HID], tt[D_HID], b2s[128];

    const int tid = threadIdx.x, lane = tid & 31, wid = tid >> 5;
    const int wm = wid & 3, wn = wid >> 2;
    const int mbase = blockIdx.y * 128;
    const int nbase = blockIdx.x * 128;

    #pragma unroll
    for (int q = 0; q < 2; q++) {
        ss[tid + q * 256] = g_s[tid + q * 256];
        tt[tid + q * 256] = g_t[tid + q * 256];
    }
    if (tid < 128) b2s[tid] = b2[nbase + tid];
    __syncthreads();

    // per-thread A pipeline state: 2 unit-groups (row, cgroup), 8 floats each
    const int ugr0 = tid >> 2,        ugc0 = tid & 3;          // unit 0*256+tid
    const int ugr1 = (256 + tid) >> 2, ugc1 = (256 + tid) & 3; // unit 1*256+tid
    uint4 pa[4];

    auto ldgA = [&](int s) {
        const char* gh = (const char*)g_h;
        const uint4* p0 = (const uint4*)(gh + (size_t)(mbase + ugr0) * 2048 + s * 128 + ugc0 * 32);
        const uint4* p1 = (const uint4*)(gh + (size_t)(mbase + ugr1) * 2048 + s * 128 + ugc1 * 32);
        pa[0] = p0[0]; pa[1] = p0[1];
        pa[2] = p1[0]; pa[3] = p1[1];
    };
    auto stsA = [&](int s, int buf) {
        #pragma unroll
        for (int g = 0; g < 2; g++) {
            int row = g ? ugr1 : ugr0, cg = g ? ugc1 : ugc0;
            float f[8];
            f[0] = __uint_as_float(pa[g * 2].x);     f[1] = __uint_as_float(pa[g * 2].y);
            f[2] = __uint_as_float(pa[g * 2].z);     f[3] = __uint_as_float(pa[g * 2].w);
            f[4] = __uint_as_float(pa[g * 2 + 1].x); f[5] = __uint_as_float(pa[g * 2 + 1].y);
            f[6] = __uint_as_float(pa[g * 2 + 1].z); f[7] = __uint_as_float(pa[g * 2 + 1].w);
            int kb = s * 32 + cg * 8;
            unsigned short hb[8], lb[8];
            #pragma unroll
            for (int e = 0; e < 8; e++) {
                float y = fmaxf(fmaf(f[e], ss[kb + e], tt[kb + e]), 0.f);
                hb[e] = f2h(y);
                lb[e] = f2h(y - h2f(hb[e]));
            }
            uint4 vh = make_uint4(pk(hb[0], hb[1]), pk(hb[2], hb[3]), pk(hb[4], hb[5]), pk(hb[6], hb[7]));
            uint4 vl = make_uint4(pk(lb[0], lb[1]), pk(lb[2], lb[3]), pk(lb[4], lb[5]), pk(lb[6], lb[7]));
            *(uint4*)(smem + SA(buf) + row * 128 + ((cg ^ (row & 7)) * 16)) = vh;
            *(uint4*)(smem + SA(buf) + row * 128 + (((cg + 4) ^ (row & 7)) * 16)) = vl;
        }
    };
    auto issueB = [&](int s, int buf) {
        const char* gB = (const char*)g_W2c;
        #pragma unroll
        for (int q = 0; q < 4; q++) {
            int u = q * 256 + tid, row = u >> 3, c = u & 7;
            cpa16(smem_u32(smem + SB(buf)) + row * 128 + ((c ^ (row & 7)) * 16),
                  gB + ((size_t)(nbase + row) * 16 + s) * 128 + c * 16);
        }
        CP_COMMIT();
    };

    // prologue
    ldgA(0);
    issueB(0, 0);
    stsA(0, 0);

    float acc[2][8][4];
    #pragma unroll
    for (int mi = 0; mi < 2; mi++)
        #pragma unroll
        for (int nf = 0; nf < 8; nf++)
            #pragma unroll
            for (int e = 0; e < 4; e++) acc[mi][nf][e] = 0.f;

    #pragma unroll 1
    for (int s = 0; s < 16; s++) {
        if (s + 1 < 16) {
            ldgA(s + 1);
            issueB(s + 1, (s + 1) & 1);
            CP_WAIT(1);
        } else {
            CP_WAIT(0);
        }
        __syncthreads();
        mma_stage(smem, s & 1, wm, wn, lane, acc);
        __syncthreads();
        if (s + 1 < 16) stsA(s + 1, (s + 1) & 1);
    }

    // ---- epilogue: +b2, stage, coalesced out write
    const int t4 = lane >> 2, tc = lane & 3;
    #pragma unroll
    for (int mi = 0; mi < 2; mi++)
        #pragma unroll
        for (int nf = 0; nf < 8; nf++) {
            int c0 = wn * 64 + nf * 8 + tc * 2;
            float bb0 = b2s[c0], bb1 = b2s[c0 + 1];
            int colc = c0 >> 2, off = (c0 & 3) * 4;
            #pragma unroll
            for (int rr = 0; rr < 2; rr++) {
                int row = wm * 32 + mi * 16 + t4 + rr * 8;
                float v0 = acc[mi][nf][rr * 2] + bb0;
                float v1 = acc[mi][nf][rr * 2 + 1] + bb1;
                *(float2*)(smem + row * 512 + ((colc ^ (row & 7)) * 16) + off) =
                    make_float2(v0, v1);
            }
        }
    __syncthreads();
    {
        char* go = (char*)out;
        #pragma unroll
        for (int q = 0; q < 16; q++) {
            int u = q * 256 + tid, row = u >> 5, c16 = u & 31;
            uint4 v = *(const uint4*)(smem + row * 512 + ((c16 ^ (row & 7)) * 16));
            *(uint4*)(go + (size_t)(mbase + row) * 1024 + nbase * 4 + c16 * 16) = v;
        }
    }
}

// ---------------- launch ----------------
extern "C" void kernel_launch(void* const* d_in, const int* in_sizes, int n_in,
                              void* d_out, int out_size) {
    const float* z     = (const float*)d_in[0];
    const void*  tbl   = d_in[1];
    const float* W1    = (const float*)d_in[2];
    const float* b1    = (const float*)d_in[3];
    const float* gamma = (const float*)d_in[4];
    const float* beta  = (const float*)d_in[5];
    const float* W2    = (const float*)d_in[6];
    const float* b2    = (const float*)d_in[7];
    float* out = (float*)d_out;

    cudaFuncSetAttribute(gemm1_kernel, cudaFuncAttributeMaxDynamicSharedMemorySize, DYN_BYTES);
    cudaFuncSetAttribute(gemm2_kernel, cudaFuncAttributeMaxDynamicSharedMemorySize, DYN_BYTES);

    prepw_kernel<<<D_HID + D_OUT, 256>>>(W1, W2);
    gather_kernel<<<M_ROWS / 8, 256>>>(z, tbl);
    gemm1_kernel<<<dim3(4, GRID_Y), 256, DYN_BYTES>>>(b1);
    stats_kernel<<<D_HID, 256>>>(gamma, beta);
    gemm2_kernel<<<dim3(2, GRID_Y), 256, DYN_BYTES>>>(b2, out);
}